// round 3
// baseline (speedup 1.0000x reference)
#include <cuda_runtime.h>
#include <cstdint>

#define BN 8
#define NN 4096
#define DD 256
#define TILE 128
#define KC 32
#define SAMPK 256

// ---------------- scratch (no allocations allowed) ----------------
__device__ float g_sq[BN * NN];      // per-point sum of squares
__device__ float g_dk2[BN * NN];     // squared distance to 5th NN
__device__ int   g_sidx[BN * SAMPK]; // sampled indices per batch

// ---------------- kernel 0: sum of squares per point ----------------
__global__ void sq_kernel(const float* __restrict__ x) {
    int row = blockIdx.x * 8 + threadIdx.y;              // 0..32767
    const float4* p = (const float4*)(x + (size_t)row * DD);
    float s = 0.f;
#pragma unroll
    for (int i = 0; i < 2; i++) {
        float4 v = p[threadIdx.x + i * 32];
        s = fmaf(v.x, v.x, fmaf(v.y, v.y, fmaf(v.z, v.z, fmaf(v.w, v.w, s))));
    }
#pragma unroll
    for (int o = 16; o; o >>= 1) s += __shfl_xor_sync(0xffffffffu, s, o);
    if (threadIdx.x == 0) g_sq[row] = s;
}

// ---------------- kernel 1: fused GEMM + per-row 5th-smallest d2 ----------------
// Block = (i_tile, batch). 256 threads as 16x16, each computes 8x8 of a 128x128
// d2 tile, streamed over 32 j-tiles; per-thread top-5 per row, merged at the end.
__global__ void __launch_bounds__(256, 1) knn_kernel(const float* __restrict__ x) {
    __shared__ __align__(16) float sm[10368]; // tiles: 2*32*132 + 128 = 8576; merge: 128*81 = 10368
#define AS(k, i) sm[(k) * 132 + (i)]
#define BS(k, j) sm[4224 + (k) * 132 + (j)]
#define SQJ(j)   sm[8448 + (j)]
#define MB(r, q) sm[(r) * 81 + (q)]

    const int b  = blockIdx.y;
    const int i0 = blockIdx.x * TILE;
    const float* xb = x + (size_t)b * NN * DD;

    const int tid = threadIdx.x;
    const int tx = tid & 15;     // column group
    const int ty = tid >> 4;     // row group

    float sqi[8];
#pragma unroll
    for (int a = 0; a < 8; a++) sqi[a] = g_sq[b * NN + i0 + ty * 8 + a];

    float t5[8][5];
#pragma unroll
    for (int a = 0; a < 8; a++)
#pragma unroll
        for (int q = 0; q < 5; q++) t5[a][q] = INFINITY;

    for (int jt = 0; jt < NN / TILE; jt++) {
        const int j0 = jt * TILE;
        __syncthreads();                 // protect SQJ/tiles from previous fold readers
        if (tid < TILE) SQJ(tid) = g_sq[b * NN + j0 + tid];

        float acc[8][8];
#pragma unroll
        for (int a = 0; a < 8; a++)
#pragma unroll
            for (int c = 0; c < 8; c++) acc[a][c] = 0.f;

        for (int kc = 0; kc < DD; kc += KC) {
            __syncthreads();
            // load 128x32 A and B chunks (transposed into [k][row]) — 4 float4 each
#pragma unroll
            for (int q = 0; q < 4; q++) {
                int l  = tid + q * 256;      // 0..1023
                int r  = l >> 3;             // row in tile
                int kv = l & 7;              // float4 index within chunk
                float4 va = *(const float4*)(xb + (size_t)(i0 + r) * DD + kc + kv * 4);
                AS(kv * 4 + 0, r) = va.x; AS(kv * 4 + 1, r) = va.y;
                AS(kv * 4 + 2, r) = va.z; AS(kv * 4 + 3, r) = va.w;
                float4 vb = *(const float4*)(xb + (size_t)(j0 + r) * DD + kc + kv * 4);
                BS(kv * 4 + 0, r) = vb.x; BS(kv * 4 + 1, r) = vb.y;
                BS(kv * 4 + 2, r) = vb.z; BS(kv * 4 + 3, r) = vb.w;
            }
            __syncthreads();
#pragma unroll
            for (int kk = 0; kk < KC; kk++) {
                float ar[8], br[8];
                float4 a0 = *(const float4*)&AS(kk, ty * 8);
                float4 a1 = *(const float4*)&AS(kk, ty * 8 + 4);
                float4 b0 = *(const float4*)&BS(kk, tx * 8);
                float4 b1 = *(const float4*)&BS(kk, tx * 8 + 4);
                ar[0]=a0.x; ar[1]=a0.y; ar[2]=a0.z; ar[3]=a0.w;
                ar[4]=a1.x; ar[5]=a1.y; ar[6]=a1.z; ar[7]=a1.w;
                br[0]=b0.x; br[1]=b0.y; br[2]=b0.z; br[3]=b0.w;
                br[4]=b1.x; br[5]=b1.y; br[6]=b1.z; br[7]=b1.w;
#pragma unroll
                for (int a = 0; a < 8; a++)
#pragma unroll
                    for (int c = 0; c < 8; c++)
                        acc[a][c] = fmaf(ar[a], br[c], acc[a][c]);
            }
        }

        // fold this 128x128 tile into per-row top-5 (match jax rounding: (sqi+sqj) - 2*s, clamp 0)
#pragma unroll
        for (int a = 0; a < 8; a++) {
            const int gi = i0 + ty * 8 + a;
#pragma unroll
            for (int c = 0; c < 8; c++) {
                const int gj = j0 + tx * 8 + c;
                float t = __fadd_rn(sqi[a], SQJ(tx * 8 + c));
                float v = __fsub_rn(t, __fmul_rn(2.0f, acc[a][c]));
                v = fmaxf(v, 0.0f);
                if (gj == gi) v = INFINITY;
                if (v < t5[a][4]) {
                    float m = v;
#pragma unroll
                    for (int q = 0; q < 5; q++) {
                        float cur = t5[a][q];
                        float lo = fminf(m, cur);
                        m = fmaxf(m, cur);
                        t5[a][q] = lo;
                    }
                }
            }
        }
    }

    // merge 16 partial top-5 lists per row -> 5th smallest
    __syncthreads();
#pragma unroll
    for (int a = 0; a < 8; a++) {
        int row = ty * 8 + a;
#pragma unroll
        for (int q = 0; q < 5; q++) MB(row, tx * 5 + q) = t5[a][q];
    }
    __syncthreads();
    if (tid < TILE) {
        float best[5] = {INFINITY, INFINITY, INFINITY, INFINITY, INFINITY};
        for (int q = 0; q < 80; q++) {
            float v = MB(tid, q);
            if (v < best[4]) {
                float m = v;
#pragma unroll
                for (int p = 0; p < 5; p++) {
                    float cur = best[p];
                    float lo = fminf(m, cur);
                    m = fmaxf(m, cur);
                    best[p] = lo;
                }
            }
        }
        g_dk2[b * NN + i0 + tid] = best[4];
    }
#undef AS
#undef BS
#undef SQJ
#undef MB
}

// ---------------- threefry2x32, key = (0, 42) ----------------
__device__ __forceinline__ uint2 threefry_0_42(unsigned x0, unsigned x1) {
    const unsigned ks0 = 0u, ks1 = 42u;
    const unsigned ks2 = 0x1BD11BDAu ^ 42u;
    x0 += ks0; x1 += ks1;
#define ROTL(v, d) (((v) << (d)) | ((v) >> (32 - (d))))
#define RND(r) { x0 += x1; x1 = ROTL(x1, r); x1 ^= x0; }
    RND(13) RND(15) RND(26) RND(6)  x0 += ks1; x1 += ks2 + 1u;
    RND(17) RND(29) RND(16) RND(24) x0 += ks2; x1 += ks0 + 2u;
    RND(13) RND(15) RND(26) RND(6)  x0 += ks0; x1 += ks1 + 3u;
    RND(17) RND(29) RND(16) RND(24) x0 += ks1; x1 += ks2 + 4u;
    RND(13) RND(15) RND(26) RND(6)  x0 += ks2; x1 += ks0 + 5u;
#undef RND
#undef ROTL
    return make_uint2(x0, x1);
}

// ---------------- kernel 2: scores + stable top-256 via bitonic sort ----------------
__global__ void score_sort_kernel() {
    __shared__ unsigned long long keys[NN];
    const int b = blockIdx.x;
    const int tid = threadIdx.x; // 1024
    const float TINY = 1.17549435e-38f;

    for (int n = tid; n < NN; n += 1024) {
        int jf = b * NN + n;
        // jax threefry_partitionable, bit_width=32:
        //   counts1, counts2 = hi/lo words of 64-bit flat iota -> (0, jf)
        //   bits1, bits2 = threefry2x32(key, counts)
        //   random bits = bits1 ^ bits2
        uint2 y = threefry_0_42(0u, (unsigned)jf);
        unsigned bits = y.x ^ y.y;
        float u = __uint_as_float((bits >> 9) | 0x3f800000u) - 1.0f;
        float val = __fadd_rn(u, TINY);          // u*(1-tiny)+tiny with (1-tiny)==1.0f
        val = fmaxf(TINY, val);
        float g = -logf(-logf(val));
        float w = sqrtf(__fadd_rn(g_dk2[jf], 1e-12f));
        float score = __fadd_rn(logf(__fadd_rn(w, 1e-12f)), g);
        unsigned s = __float_as_uint(score);
        unsigned mono = (s & 0x80000000u) ? ~s : (s | 0x80000000u);
        keys[n] = ((unsigned long long)(~mono) << 32) | (unsigned)n; // asc sort => desc score, ties -> low idx
    }
    __syncthreads();

    for (int k = 2; k <= NN; k <<= 1) {
        for (int j = k >> 1; j > 0; j >>= 1) {
            for (int i = tid; i < NN; i += 1024) {
                int ixj = i ^ j;
                if (ixj > i) {
                    bool up = ((i & k) == 0);
                    unsigned long long a = keys[i], c = keys[ixj];
                    if ((a > c) == up) { keys[i] = c; keys[ixj] = a; }
                }
            }
            __syncthreads();
        }
    }
    if (tid < SAMPK) g_sidx[b * SAMPK + tid] = (int)(keys[tid] & 0xffffffffu);
}

// ---------------- kernel 3: gather + tail zero ----------------
__global__ void gather_kernel(const float* __restrict__ x, float* __restrict__ out, int out_size) {
    long gid = (long)blockIdx.x * 256 + threadIdx.x;
    if (gid >= out_size) return;
    const long SAMP = (long)BN * SAMPK * DD;
    if (gid < SAMP) {
        int d = (int)(gid & 255);
        int s = (int)((gid >> 8) & 255);
        int b = (int)(gid >> 16);
        int idx = g_sidx[b * SAMPK + s];
        out[gid] = x[((size_t)b * NN + idx) * DD + d];
    } else {
        out[gid] = 0.0f;
    }
}

// ---------------- launch ----------------
extern "C" void kernel_launch(void* const* d_in, const int* in_sizes, int n_in,
                              void* d_out, int out_size) {
    const float* x = (const float*)d_in[0];
    float* out = (float*)d_out;

    dim3 sqb(32, 8);
    sq_kernel<<<BN * NN / 8, sqb>>>(x);

    dim3 g1(NN / TILE, BN);
    knn_kernel<<<g1, 256>>>(x);

    score_sort_kernel<<<BN, 1024>>>();

    long total = out_size;
    gather_kernel<<<(unsigned)((total + 255) / 256), 256>>>(x, out, (int)total);
}

// round 5
// speedup vs baseline: 1.8346x; 1.8346x over previous
#include <cuda_runtime.h>
#include <cuda_fp16.h>
#include <cstdint>

#define BN 8
#define NN 4096
#define DD 256
#define SAMPK 256
#define KEXT 768
#define NCHK 12          // 768 / 64
#define JQ 4             // j-quarters
#define JSTEPS 8         // 128-col steps per quarter
#define NCH (JSTEPS * NCHK)

// ---------------- scratch (no allocations allowed) ----------------
__device__ float g_sq[BN * NN];
__device__ float g_dk2[BN * NN];
__device__ int   g_sidx[BN * SAMPK];
__device__ __half g_xa[(size_t)BN * NN * KEXT];   // [hi | hi | lo]
__device__ __half g_xb[(size_t)BN * NN * KEXT];   // [hi | lo | hi]
__device__ float g_part[(size_t)JQ * BN * NN * 5];

// ---------------- kernel A: fp32 -> extended fp16 operands ----------------
__global__ void cvt_kernel(const float* __restrict__ x) {
    size_t gid = ((size_t)blockIdx.x * 256 + threadIdx.x);
    size_t row = gid >> 6;            // 64 threads per 256-elem row
    int    k   = ((int)gid & 63) * 4;
    float4 v = *(const float4*)(x + row * DD + k);
    float f[4] = {v.x, v.y, v.z, v.w};
    __half h[4], l[4];
#pragma unroll
    for (int i = 0; i < 4; i++) {
        h[i] = __float2half_rn(f[i]);
        l[i] = __float2half_rn(f[i] - __half2float(h[i]));
    }
    uint2 uh = make_uint2(
        (uint32_t)__half_as_ushort(h[0]) | ((uint32_t)__half_as_ushort(h[1]) << 16),
        (uint32_t)__half_as_ushort(h[2]) | ((uint32_t)__half_as_ushort(h[3]) << 16));
    uint2 ul = make_uint2(
        (uint32_t)__half_as_ushort(l[0]) | ((uint32_t)__half_as_ushort(l[1]) << 16),
        (uint32_t)__half_as_ushort(l[2]) | ((uint32_t)__half_as_ushort(l[3]) << 16));
    unsigned short* xa = (unsigned short*)g_xa + row * KEXT;
    unsigned short* xb = (unsigned short*)g_xb + row * KEXT;
    *(uint2*)(xa + k)       = uh;   // A: hi
    *(uint2*)(xa + 256 + k) = uh;   // A: hi
    *(uint2*)(xa + 512 + k) = ul;   // A: lo
    *(uint2*)(xb + k)       = uh;   // B: hi
    *(uint2*)(xb + 256 + k) = ul;   // B: lo
    *(uint2*)(xb + 512 + k) = uh;   // B: hi
}

// ---------------- kernel B: sum of squares per point ----------------
__global__ void sq_kernel(const float* __restrict__ x) {
    int row = blockIdx.x * 8 + threadIdx.y;
    const float4* p = (const float4*)(x + (size_t)row * DD);
    float s = 0.f;
#pragma unroll
    for (int i = 0; i < 2; i++) {
        float4 v = p[threadIdx.x + i * 32];
        s = fmaf(v.x, v.x, fmaf(v.y, v.y, fmaf(v.z, v.z, fmaf(v.w, v.w, s))));
    }
#pragma unroll
    for (int o = 16; o; o >>= 1) s += __shfl_xor_sync(0xffffffffu, s, o);
    if (threadIdx.x == 0) g_sq[row] = s;
}

// ---------------- kernel C: mma.sync GEMM + fused kNN top-5 ----------------
// grid (32 i-tiles, 4 j-quarters, 8 batches), 256 threads = 8 warps (2 M x 4 N),
// warp tile 64x32, K-chunks of 64 fp16, 3-stage cp.async pipeline.
#define STAGE_B 32768
#define KNN_SMEM (3 * STAGE_B)

__device__ __forceinline__ void ldmx4(uint32_t* r, uint32_t addr) {
    asm volatile("ldmatrix.sync.aligned.m8n8.x4.shared.b16 {%0,%1,%2,%3}, [%4];"
                 : "=r"(r[0]), "=r"(r[1]), "=r"(r[2]), "=r"(r[3]) : "r"(addr));
}
__device__ __forceinline__ void mma16816(float* d, const uint32_t* a, const uint32_t* b) {
    asm volatile("mma.sync.aligned.m16n8k16.row.col.f32.f16.f16.f32 "
                 "{%0,%1,%2,%3}, {%4,%5,%6,%7}, {%8,%9}, {%0,%1,%2,%3};"
                 : "+f"(d[0]), "+f"(d[1]), "+f"(d[2]), "+f"(d[3])
                 : "r"(a[0]), "r"(a[1]), "r"(a[2]), "r"(a[3]), "r"(b[0]), "r"(b[1]));
}
__device__ __forceinline__ void cp16(uint32_t dst, const void* src) {
    asm volatile("cp.async.cg.shared.global [%0], [%1], 16;" :: "r"(dst), "l"(src) : "memory");
}

__global__ void __launch_bounds__(256, 1) knn_mma_kernel() {
    extern __shared__ __align__(128) char sm[];
    uint32_t smb;
    asm("{ .reg .u64 t; cvta.to.shared.u64 t, %1; cvt.u32.u64 %0, t; }" : "=r"(smb) : "l"(sm));

    const int tid = threadIdx.x;
    const int lane = tid & 31;
    const int warp = tid >> 5;
    const int wm = warp & 1;       // 0..1 (M)
    const int wn = warp >> 1;      // 0..3 (N)
    const int b  = blockIdx.z;
    const int i0 = blockIdx.x * 128;
    const int jq = blockIdx.y;

    // loader mapping: 2 threads per row, 4x16B each
    const int lr  = tid >> 1;
    const int lq4 = (tid & 1) * 4;
    uint32_t soff[4];
#pragma unroll
    for (int i = 0; i < 4; i++)
        soff[i] = (uint32_t)(lr * 128 + (((lq4 + i) ^ (lr & 7)) * 16));
    const __half* asrc0 = g_xa + ((size_t)(b * NN + i0 + lr)) * KEXT + lq4 * 8;
    const __half* bsrc0 = g_xb + ((size_t)(b * NN + lr)) * KEXT + lq4 * 8;

    // per-thread row info (8 row-slots: s = m*2 + h)
    float sqi[8]; int gi[8];
#pragma unroll
    for (int m = 0; m < 4; m++)
#pragma unroll
        for (int h = 0; h < 2; h++) {
            int s = m * 2 + h;
            gi[s] = i0 + wm * 64 + m * 16 + (lane >> 2) + h * 8;
            sqi[s] = g_sq[b * NN + gi[s]];
        }
    float t5[8][5];
#pragma unroll
    for (int s = 0; s < 8; s++)
#pragma unroll
        for (int q = 0; q < 5; q++) t5[s][q] = INFINITY;

    float acc[4][4][4];

    // ---- pipeline ----
    auto issue = [&](int c) {
        const int js = c / NCHK, kc = (c % NCHK) * 64;
        const uint32_t base = smb + (c % 3) * STAGE_B;
        const __half* as = asrc0 + kc;
        const __half* bs = bsrc0 + ((size_t)((jq * JSTEPS + js) * 128)) * KEXT + kc;
#pragma unroll
        for (int i = 0; i < 4; i++) cp16(base + soff[i], as + i * 8);
#pragma unroll
        for (int i = 0; i < 4; i++) cp16(base + 16384 + soff[i], bs + i * 8);
        asm volatile("cp.async.commit_group;" ::: "memory");
    };

    issue(0);
    issue(1);

    for (int c = 0; c < NCH; c++) {
        if (c == NCH - 1) asm volatile("cp.async.wait_group 0;" ::: "memory");
        else              asm volatile("cp.async.wait_group 1;" ::: "memory");
        __syncthreads();
        if (c + 2 < NCH) issue(c + 2);

        const uint32_t Ab = smb + (c % 3) * STAGE_B;
        const uint32_t Bb = Ab + 16384;

        if (c % NCHK == 0) {
#pragma unroll
            for (int m = 0; m < 4; m++)
#pragma unroll
                for (int n = 0; n < 4; n++)
#pragma unroll
                    for (int v = 0; v < 4; v++) acc[m][n][v] = 0.f;
        }

#pragma unroll
        for (int k16 = 0; k16 < 4; k16++) {
            uint32_t afr[4][4], bfr[4][2];
#pragma unroll
            for (int m = 0; m < 4; m++) {
                int R = wm * 64 + m * 16 + (lane & 15);
                int ul = k16 * 2 + (lane >> 4);
                ldmx4(afr[m], Ab + R * 128 + ((ul ^ (R & 7)) * 16));
            }
#pragma unroll
            for (int np = 0; np < 2; np++) {
                int RB = wn * 32 + np * 16 + ((lane >> 4) << 3) + (lane & 7);
                int ul = k16 * 2 + ((lane >> 3) & 1);
                uint32_t r[4];
                ldmx4(r, Bb + RB * 128 + ((ul ^ (RB & 7)) * 16));
                bfr[np * 2][0] = r[0]; bfr[np * 2][1] = r[1];
                bfr[np * 2 + 1][0] = r[2]; bfr[np * 2 + 1][1] = r[3];
            }
#pragma unroll
            for (int m = 0; m < 4; m++)
#pragma unroll
                for (int n = 0; n < 4; n++)
                    mma16816(acc[m][n], afr[m], bfr[n]);
        }

        if (c % NCHK == NCHK - 1) {
            const int js = c / NCHK;
            const int j0 = (jq * JSTEPS + js) * 128;
#pragma unroll
            for (int n = 0; n < 4; n++)
#pragma unroll
                for (int cc = 0; cc < 2; cc++) {
                    int gj = j0 + wn * 32 + n * 8 + (lane & 3) * 2 + cc;
                    float sqj = __ldg(&g_sq[b * NN + gj]);
#pragma unroll
                    for (int m = 0; m < 4; m++)
#pragma unroll
                        for (int h = 0; h < 2; h++) {
                            int s = m * 2 + h;
                            float G = acc[m][n][h * 2 + cc];
                            float v = __fsub_rn(__fadd_rn(sqi[s], sqj), __fmul_rn(2.0f, G));
                            v = fmaxf(v, 0.0f);
                            if (gj == gi[s]) v = INFINITY;
                            if (v < t5[s][4]) {
                                float mm = v;
#pragma unroll
                                for (int q = 0; q < 5; q++) {
                                    float cur = t5[s][q];
                                    float lo = fminf(mm, cur);
                                    mm = fmaxf(mm, cur);
                                    t5[s][q] = lo;
                                }
                            }
                        }
                }
        }
    }

    // ---- merge 16 owners per row via smem ----
    __syncthreads();
    float* MS = (float*)sm;   // 128 rows x 16 owners x 5
    const int owner = wn * 4 + (lane & 3);
#pragma unroll
    for (int s = 0; s < 8; s++) {
        int rloc = gi[s] - i0;
#pragma unroll
        for (int q = 0; q < 5; q++) MS[rloc * 80 + owner * 5 + q] = t5[s][q];
    }
    __syncthreads();
    if (tid < 128) {
        float best[5] = {INFINITY, INFINITY, INFINITY, INFINITY, INFINITY};
        for (int k = 0; k < 80; k++) {
            float v = MS[tid * 80 + k];
            if (v < best[4]) {
                float mm = v;
#pragma unroll
                for (int q = 0; q < 5; q++) {
                    float cur = best[q];
                    float lo = fminf(mm, cur);
                    mm = fmaxf(mm, cur);
                    best[q] = lo;
                }
            }
        }
        size_t o = ((size_t)jq * BN * NN + (size_t)b * NN + i0 + tid) * 5;
#pragma unroll
        for (int q = 0; q < 5; q++) g_part[o + q] = best[q];
    }
}

// ---------------- kernel C2: merge j-quarter partials ----------------
__global__ void merge_kernel() {
    int r = blockIdx.x * 256 + threadIdx.x;   // b*NN + i
    float best[5] = {INFINITY, INFINITY, INFINITY, INFINITY, INFINITY};
#pragma unroll
    for (int jq = 0; jq < JQ; jq++) {
        size_t o = ((size_t)jq * BN * NN + r) * 5;
#pragma unroll
        for (int q = 0; q < 5; q++) {
            float v = g_part[o + q];
            if (v < best[4]) {
                float mm = v;
#pragma unroll
                for (int p = 0; p < 5; p++) {
                    float cur = best[p];
                    float lo = fminf(mm, cur);
                    mm = fmaxf(mm, cur);
                    best[p] = lo;
                }
            }
        }
    }
    g_dk2[r] = best[4];
}

// ---------------- threefry2x32, key = (0, 42) ----------------
__device__ __forceinline__ uint2 threefry_0_42(unsigned x0, unsigned x1) {
    const unsigned ks0 = 0u, ks1 = 42u;
    const unsigned ks2 = 0x1BD11BDAu ^ 42u;
    x0 += ks0; x1 += ks1;
#define ROTL(v, d) (((v) << (d)) | ((v) >> (32 - (d))))
#define RND(r) { x0 += x1; x1 = ROTL(x1, r); x1 ^= x0; }
    RND(13) RND(15) RND(26) RND(6)  x0 += ks1; x1 += ks2 + 1u;
    RND(17) RND(29) RND(16) RND(24) x0 += ks2; x1 += ks0 + 2u;
    RND(13) RND(15) RND(26) RND(6)  x0 += ks0; x1 += ks1 + 3u;
    RND(17) RND(29) RND(16) RND(24) x0 += ks1; x1 += ks2 + 4u;
    RND(13) RND(15) RND(26) RND(6)  x0 += ks2; x1 += ks0 + 5u;
#undef RND
#undef ROTL
    return make_uint2(x0, x1);
}

// ---------------- kernel D: scores + stable top-256 via bitonic sort ----------------
__global__ void score_sort_kernel() {
    __shared__ unsigned long long keys[NN];
    const int b = blockIdx.x;
    const int tid = threadIdx.x; // 1024
    const float TINY = 1.17549435e-38f;

    for (int n = tid; n < NN; n += 1024) {
        int jf = b * NN + n;
        uint2 y = threefry_0_42(0u, (unsigned)jf);
        unsigned bits = y.x ^ y.y;
        float u = __uint_as_float((bits >> 9) | 0x3f800000u) - 1.0f;
        float val = fmaxf(TINY, __fadd_rn(u, TINY));
        float g = -logf(-logf(val));
        float w = sqrtf(__fadd_rn(g_dk2[jf], 1e-12f));
        float score = __fadd_rn(logf(__fadd_rn(w, 1e-12f)), g);
        unsigned s = __float_as_uint(score);
        unsigned mono = (s & 0x80000000u) ? ~s : (s | 0x80000000u);
        keys[n] = ((unsigned long long)(~mono) << 32) | (unsigned)n;
    }
    __syncthreads();

    for (int k = 2; k <= NN; k <<= 1) {
        for (int j = k >> 1; j > 0; j >>= 1) {
            for (int i = tid; i < NN; i += 1024) {
                int ixj = i ^ j;
                if (ixj > i) {
                    bool up = ((i & k) == 0);
                    unsigned long long a = keys[i], c = keys[ixj];
                    if ((a > c) == up) { keys[i] = c; keys[ixj] = a; }
                }
            }
            __syncthreads();
        }
    }
    if (tid < SAMPK) g_sidx[b * SAMPK + tid] = (int)(keys[tid] & 0xffffffffu);
}

// ---------------- kernel E: gather + tail zero ----------------
__global__ void gather_kernel(const float* __restrict__ x, float* __restrict__ out, int out_size) {
    long gid = (long)blockIdx.x * 256 + threadIdx.x;
    if (gid >= out_size) return;
    const long SAMP = (long)BN * SAMPK * DD;
    if (gid < SAMP) {
        int d = (int)(gid & 255);
        int s = (int)((gid >> 8) & 255);
        int bb = (int)(gid >> 16);
        int idx = g_sidx[bb * SAMPK + s];
        out[gid] = x[((size_t)bb * NN + idx) * DD + d];
    } else {
        out[gid] = 0.0f;
    }
}

// ---------------- launch ----------------
extern "C" void kernel_launch(void* const* d_in, const int* in_sizes, int n_in,
                              void* d_out, int out_size) {
    const float* x = (const float*)d_in[0];
    float* out = (float*)d_out;

    static bool configured = false;
    if (!configured) {
        cudaFuncSetAttribute(knn_mma_kernel, cudaFuncAttributeMaxDynamicSharedMemorySize, KNN_SMEM);
        configured = true;
    }

    cvt_kernel<<<(BN * NN * DD) / (256 * 4), 256>>>(x);

    dim3 sqb(32, 8);
    sq_kernel<<<BN * NN / 8, sqb>>>(x);

    dim3 g1(NN / 128, JQ, BN);
    knn_mma_kernel<<<g1, 256, KNN_SMEM>>>();

    merge_kernel<<<BN * NN / 256, 256>>>();

    score_sort_kernel<<<BN, 1024>>>();

    long total = out_size;
    gather_kernel<<<(unsigned)((total + 255) / 256), 256>>>(x, out, (int)total);
}

// round 6
// speedup vs baseline: 2.6583x; 1.4490x over previous
#include <cuda_runtime.h>
#include <cuda_fp16.h>
#include <cstdint>

#define BN 8
#define NN 4096
#define DD 256
#define SAMPK 256
#define KEXT 768
#define NCH 12           // K chunks of 64
#define JB 16            // j-blocks of 256 cols
#define STAGE_B 49152
#define KNN_SMEM (4 * STAGE_B)

// ---------------- scratch (no allocations allowed) ----------------
__device__ float g_sq[BN * NN];
__device__ float g_dk2[BN * NN];
__device__ int   g_sidx[BN * SAMPK];
__device__ __half g_xa[(size_t)BN * NN * KEXT];   // [hi | hi | lo]
__device__ __half g_xb[(size_t)BN * NN * KEXT];   // [hi | lo | hi]
__device__ float g_part[(size_t)JB * BN * NN * 5];

// ---------------- kernel A: fp32 -> extended fp16 operands ----------------
__global__ void cvt_kernel(const float* __restrict__ x) {
    size_t gid = ((size_t)blockIdx.x * 256 + threadIdx.x);
    size_t row = gid >> 6;
    int    k   = ((int)gid & 63) * 4;
    float4 v = *(const float4*)(x + row * DD + k);
    float f[4] = {v.x, v.y, v.z, v.w};
    __half h[4], l[4];
#pragma unroll
    for (int i = 0; i < 4; i++) {
        h[i] = __float2half_rn(f[i]);
        l[i] = __float2half_rn(f[i] - __half2float(h[i]));
    }
    uint2 uh = make_uint2(
        (uint32_t)__half_as_ushort(h[0]) | ((uint32_t)__half_as_ushort(h[1]) << 16),
        (uint32_t)__half_as_ushort(h[2]) | ((uint32_t)__half_as_ushort(h[3]) << 16));
    uint2 ul = make_uint2(
        (uint32_t)__half_as_ushort(l[0]) | ((uint32_t)__half_as_ushort(l[1]) << 16),
        (uint32_t)__half_as_ushort(l[2]) | ((uint32_t)__half_as_ushort(l[3]) << 16));
    unsigned short* xa = (unsigned short*)g_xa + row * KEXT;
    unsigned short* xb = (unsigned short*)g_xb + row * KEXT;
    *(uint2*)(xa + k)       = uh;
    *(uint2*)(xa + 256 + k) = uh;
    *(uint2*)(xa + 512 + k) = ul;
    *(uint2*)(xb + k)       = uh;
    *(uint2*)(xb + 256 + k) = ul;
    *(uint2*)(xb + 512 + k) = uh;
}

// ---------------- kernel B: sum of squares per point ----------------
__global__ void sq_kernel(const float* __restrict__ x) {
    int row = blockIdx.x * 8 + threadIdx.y;
    const float4* p = (const float4*)(x + (size_t)row * DD);
    float s = 0.f;
#pragma unroll
    for (int i = 0; i < 2; i++) {
        float4 v = p[threadIdx.x + i * 32];
        s = fmaf(v.x, v.x, fmaf(v.y, v.y, fmaf(v.z, v.z, fmaf(v.w, v.w, s))));
    }
#pragma unroll
    for (int o = 16; o; o >>= 1) s += __shfl_xor_sync(0xffffffffu, s, o);
    if (threadIdx.x == 0) g_sq[row] = s;
}

// ---------------- mma helpers ----------------
__device__ __forceinline__ void ldmx4(uint32_t* r, uint32_t addr) {
    asm volatile("ldmatrix.sync.aligned.m8n8.x4.shared.b16 {%0,%1,%2,%3}, [%4];"
                 : "=r"(r[0]), "=r"(r[1]), "=r"(r[2]), "=r"(r[3]) : "r"(addr));
}
__device__ __forceinline__ void mma16816(float* d, const uint32_t* a, const uint32_t* b) {
    asm volatile("mma.sync.aligned.m16n8k16.row.col.f32.f16.f16.f32 "
                 "{%0,%1,%2,%3}, {%4,%5,%6,%7}, {%8,%9}, {%0,%1,%2,%3};"
                 : "+f"(d[0]), "+f"(d[1]), "+f"(d[2]), "+f"(d[3])
                 : "r"(a[0]), "r"(a[1]), "r"(a[2]), "r"(a[3]), "r"(b[0]), "r"(b[1]));
}
__device__ __forceinline__ void cp16(uint32_t dst, const void* src) {
    asm volatile("cp.async.cg.shared.global [%0], [%1], 16;" :: "r"(dst), "l"(src) : "memory");
}

// ---------------- kernel C: mma.sync GEMM + fused kNN top-5 ----------------
// grid (16 j-blocks, 32 i-tiles, 8 batches), 512 threads = 16 warps (4 M x 4 N),
// block tile 128x256, warp tile 32x64, K-chunks of 64 fp16, 4-stage cp.async.
__global__ void __launch_bounds__(512, 1) knn_mma_kernel() {
    extern __shared__ __align__(128) char sm[];
    uint32_t smb;
    asm("{ .reg .u64 t; cvta.to.shared.u64 t, %1; cvt.u32.u64 %0, t; }" : "=r"(smb) : "l"(sm));

    const int tid = threadIdx.x;
    const int lane = tid & 31;
    const int warp = tid >> 5;
    const int wm = warp & 3;       // 0..3 (M, 32 rows each)
    const int wn = warp >> 2;      // 0..3 (N, 64 cols each)
    const int jb = blockIdx.x;
    const int b  = blockIdx.z;
    const int i0 = blockIdx.y * 128;
    const int j0 = jb * 256;

    // loader precompute: 6 x 16B per thread (A: 1024 units, B: 2048 units)
    uint32_t soff[6];
    const __half* src[6];
#pragma unroll
    for (int k = 0; k < 6; k++) {
        int u = tid + k * 512;
        int row = u >> 3, q = u & 7;
        soff[k] = (uint32_t)(row * 128 + ((q ^ (row & 7)) * 16));
        if (row < 128) src[k] = g_xa + ((size_t)(b * NN + i0 + row)) * KEXT + q * 8;
        else           src[k] = g_xb + ((size_t)(b * NN + j0 + (row - 128))) * KEXT + q * 8;
    }
    auto issue = [&](int c) {
        const uint32_t base = smb + (c & 3) * STAGE_B;
#pragma unroll
        for (int k = 0; k < 6; k++)
            cp16(base + soff[k], src[k] + c * 64);
        asm volatile("cp.async.commit_group;" ::: "memory");
    };

    float acc[2][8][4];
#pragma unroll
    for (int mi = 0; mi < 2; mi++)
#pragma unroll
        for (int ni = 0; ni < 8; ni++)
#pragma unroll
            for (int v = 0; v < 4; v++) acc[mi][ni][v] = 0.f;

    issue(0); issue(1); issue(2);

    for (int c = 0; c < NCH; c++) {
        if (c < NCH - 2)       asm volatile("cp.async.wait_group 2;" ::: "memory");
        else if (c == NCH - 2) asm volatile("cp.async.wait_group 1;" ::: "memory");
        else                   asm volatile("cp.async.wait_group 0;" ::: "memory");
        __syncthreads();

        const uint32_t Ab = smb + (c & 3) * STAGE_B;
        const uint32_t Bb = Ab + 16384;

#pragma unroll
        for (int k16 = 0; k16 < 4; k16++) {
            uint32_t afr[2][4], bfr[8][2];
#pragma unroll
            for (int mi = 0; mi < 2; mi++) {
                int R = wm * 32 + mi * 16 + (lane & 15);
                int ul = k16 * 2 + (lane >> 4);
                ldmx4(afr[mi], Ab + R * 128 + ((ul ^ (R & 7)) * 16));
            }
#pragma unroll
            for (int np = 0; np < 4; np++) {
                int RB = wn * 64 + np * 16 + ((lane >> 4) << 3) + (lane & 7);
                int ul = k16 * 2 + ((lane >> 3) & 1);
                uint32_t r[4];
                ldmx4(r, Bb + RB * 128 + ((ul ^ (RB & 7)) * 16));
                bfr[np * 2][0] = r[0]; bfr[np * 2][1] = r[1];
                bfr[np * 2 + 1][0] = r[2]; bfr[np * 2 + 1][1] = r[3];
            }
#pragma unroll
            for (int mi = 0; mi < 2; mi++)
#pragma unroll
                for (int ni = 0; ni < 8; ni++)
                    mma16816(acc[mi][ni], afr[mi], bfr[ni]);
        }
        if (c + 3 < NCH) issue(c + 3);
    }

    // ---- fold 128x256 tile into per-row top-5 ----
    int gi[4]; float sqi[4];
#pragma unroll
    for (int mi = 0; mi < 2; mi++)
#pragma unroll
        for (int h = 0; h < 2; h++) {
            int s = mi * 2 + h;
            gi[s] = i0 + wm * 32 + mi * 16 + (lane >> 2) + h * 8;
            sqi[s] = g_sq[b * NN + gi[s]];
        }
    float t5[4][5];
#pragma unroll
    for (int s = 0; s < 4; s++)
#pragma unroll
        for (int q = 0; q < 5; q++) t5[s][q] = INFINITY;

#pragma unroll
    for (int ni = 0; ni < 8; ni++)
#pragma unroll
        for (int cc = 0; cc < 2; cc++) {
            int gj = j0 + wn * 64 + ni * 8 + (lane & 3) * 2 + cc;
            float sqj = __ldg(&g_sq[b * NN + gj]);
#pragma unroll
            for (int mi = 0; mi < 2; mi++)
#pragma unroll
                for (int h = 0; h < 2; h++) {
                    int s = mi * 2 + h;
                    float G = acc[mi][ni][h * 2 + cc];
                    float v = __fsub_rn(__fadd_rn(sqi[s], sqj), __fmul_rn(2.0f, G));
                    v = fmaxf(v, 0.0f);
                    if (gj == gi[s]) v = INFINITY;
                    if (v < t5[s][4]) {
                        float mm = v;
#pragma unroll
                        for (int q = 0; q < 5; q++) {
                            float cur = t5[s][q];
                            float lo = fminf(mm, cur);
                            mm = fmaxf(mm, cur);
                            t5[s][q] = lo;
                        }
                    }
                }
        }

    // ---- merge 16 owners per row via smem ----
    __syncthreads();
    float* MS = (float*)sm;   // 128 rows x 16 owners x 5 = 40KB
    const int owner = wn * 4 + (lane & 3);
#pragma unroll
    for (int s = 0; s < 4; s++) {
        int rloc = gi[s] - i0;
#pragma unroll
        for (int q = 0; q < 5; q++) MS[rloc * 80 + owner * 5 + q] = t5[s][q];
    }
    __syncthreads();
    if (tid < 128) {
        float best[5] = {INFINITY, INFINITY, INFINITY, INFINITY, INFINITY};
        for (int k = 0; k < 80; k++) {
            float v = MS[tid * 80 + k];
            if (v < best[4]) {
                float mm = v;
#pragma unroll
                for (int q = 0; q < 5; q++) {
                    float cur = best[q];
                    float lo = fminf(mm, cur);
                    mm = fmaxf(mm, cur);
                    best[q] = lo;
                }
            }
        }
        size_t o = ((size_t)jb * BN * NN + (size_t)b * NN + i0 + tid) * 5;
#pragma unroll
        for (int q = 0; q < 5; q++) g_part[o + q] = best[q];
    }
}

// ---------------- kernel C2: merge j-block partials ----------------
__global__ void merge_kernel() {
    int r = blockIdx.x * 256 + threadIdx.x;   // b*NN + i
    float best[5] = {INFINITY, INFINITY, INFINITY, INFINITY, INFINITY};
#pragma unroll
    for (int jb = 0; jb < JB; jb++) {
        size_t o = ((size_t)jb * BN * NN + r) * 5;
#pragma unroll
        for (int q = 0; q < 5; q++) {
            float v = g_part[o + q];
            if (v < best[4]) {
                float mm = v;
#pragma unroll
                for (int p = 0; p < 5; p++) {
                    float cur = best[p];
                    float lo = fminf(mm, cur);
                    mm = fmaxf(mm, cur);
                    best[p] = lo;
                }
            }
        }
    }
    g_dk2[r] = best[4];
}

// ---------------- threefry2x32, key = (0, 42) ----------------
__device__ __forceinline__ uint2 threefry_0_42(unsigned x0, unsigned x1) {
    const unsigned ks0 = 0u, ks1 = 42u;
    const unsigned ks2 = 0x1BD11BDAu ^ 42u;
    x0 += ks0; x1 += ks1;
#define ROTL(v, d) (((v) << (d)) | ((v) >> (32 - (d))))
#define RND(r) { x0 += x1; x1 = ROTL(x1, r); x1 ^= x0; }
    RND(13) RND(15) RND(26) RND(6)  x0 += ks1; x1 += ks2 + 1u;
    RND(17) RND(29) RND(16) RND(24) x0 += ks2; x1 += ks0 + 2u;
    RND(13) RND(15) RND(26) RND(6)  x0 += ks0; x1 += ks1 + 3u;
    RND(17) RND(29) RND(16) RND(24) x0 += ks1; x1 += ks2 + 4u;
    RND(13) RND(15) RND(26) RND(6)  x0 += ks2; x1 += ks0 + 5u;
#undef RND
#undef ROTL
    return make_uint2(x0, x1);
}

// ---------------- kernel D: scores + stable top-256 via bitonic sort ----------------
__global__ void score_sort_kernel() {
    __shared__ unsigned long long keys[NN];
    const int b = blockIdx.x;
    const int tid = threadIdx.x; // 1024
    const float TINY = 1.17549435e-38f;

    for (int n = tid; n < NN; n += 1024) {
        int jf = b * NN + n;
        uint2 y = threefry_0_42(0u, (unsigned)jf);
        unsigned bits = y.x ^ y.y;
        float u = __uint_as_float((bits >> 9) | 0x3f800000u) - 1.0f;
        float val = fmaxf(TINY, __fadd_rn(u, TINY));
        float g = -logf(-logf(val));
        float w = sqrtf(__fadd_rn(g_dk2[jf], 1e-12f));
        float score = __fadd_rn(logf(__fadd_rn(w, 1e-12f)), g);
        unsigned s = __float_as_uint(score);
        unsigned mono = (s & 0x80000000u) ? ~s : (s | 0x80000000u);
        keys[n] = ((unsigned long long)(~mono) << 32) | (unsigned)n;
    }
    __syncthreads();

    for (int k = 2; k <= NN; k <<= 1) {
        for (int j = k >> 1; j > 0; j >>= 1) {
            for (int i = tid; i < NN; i += 1024) {
                int ixj = i ^ j;
                if (ixj > i) {
                    bool up = ((i & k) == 0);
                    unsigned long long a = keys[i], c = keys[ixj];
                    if ((a > c) == up) { keys[i] = c; keys[ixj] = a; }
                }
            }
            __syncthreads();
        }
    }
    if (tid < SAMPK) g_sidx[b * SAMPK + tid] = (int)(keys[tid] & 0xffffffffu);
}

// ---------------- kernel E: gather + tail zero ----------------
__global__ void gather_kernel(const float* __restrict__ x, float* __restrict__ out, int out_size) {
    long gid = (long)blockIdx.x * 256 + threadIdx.x;
    if (gid >= out_size) return;
    const long SAMP = (long)BN * SAMPK * DD;
    if (gid < SAMP) {
        int d = (int)(gid & 255);
        int s = (int)((gid >> 8) & 255);
        int bb = (int)(gid >> 16);
        int idx = g_sidx[bb * SAMPK + s];
        out[gid] = x[((size_t)bb * NN + idx) * DD + d];
    } else {
        out[gid] = 0.0f;
    }
}

// ---------------- launch ----------------
extern "C" void kernel_launch(void* const* d_in, const int* in_sizes, int n_in,
                              void* d_out, int out_size) {
    const float* x = (const float*)d_in[0];
    float* out = (float*)d_out;

    static bool configured = false;
    if (!configured) {
        cudaFuncSetAttribute(knn_mma_kernel, cudaFuncAttributeMaxDynamicSharedMemorySize, KNN_SMEM);
        configured = true;
    }

    cvt_kernel<<<(BN * NN * DD) / (256 * 4), 256>>>(x);

    dim3 sqb(32, 8);
    sq_kernel<<<BN * NN / 8, sqb>>>(x);

    dim3 g1(JB, NN / 128, BN);
    knn_mma_kernel<<<g1, 512, KNN_SMEM>>>();

    merge_kernel<<<BN * NN / 256, 256>>>();

    score_sort_kernel<<<BN, 1024>>>();

    long total = out_size;
    gather_kernel<<<(unsigned)((total + 255) / 256), 256>>>(x, out, (int)total);
}

// round 7
// speedup vs baseline: 3.7172x; 1.3983x over previous
#include <cuda_runtime.h>
#include <cuda_fp16.h>
#include <cstdint>

#define BN 8
#define NN 4096
#define DD 256
#define SAMPK 256
#define KHL 512          // stored halfs per row: [hi | lo]
#define NCH 12           // K chunks of 64 (hi.hi x4, hi.lo x4, lo.hi x4)
#define NSTRIPE 272      // upper-triangle stripes per batch
#define STAGE_B 49152
#define KNN_SMEM (4 * STAGE_B)
#define MS_OFF  0
#define BUF_OFF 49152
#define BUF_STRIDE 133
#define CM_OFF  120832

// ---------------- scratch (no allocations allowed) ----------------
__device__ float g_sq[BN * NN];
__device__ float g_dk2[BN * NN];
__device__ int   g_sidx[BN * SAMPK];
__device__ __half g_x16[(size_t)BN * NN * KHL];
__device__ float g_part[(size_t)48 * BN * NN * 5];

// ---------------- kernel A: fp32 -> fp16 hi/lo split ----------------
__global__ void cvt_kernel(const float* __restrict__ x) {
    size_t gid = ((size_t)blockIdx.x * 256 + threadIdx.x);
    size_t row = gid >> 6;
    int    k   = ((int)gid & 63) * 4;
    float4 v = *(const float4*)(x + row * DD + k);
    float f[4] = {v.x, v.y, v.z, v.w};
    __half h[4], l[4];
#pragma unroll
    for (int i = 0; i < 4; i++) {
        h[i] = __float2half_rn(f[i]);
        l[i] = __float2half_rn(f[i] - __half2float(h[i]));
    }
    uint2 uh = make_uint2(
        (uint32_t)__half_as_ushort(h[0]) | ((uint32_t)__half_as_ushort(h[1]) << 16),
        (uint32_t)__half_as_ushort(h[2]) | ((uint32_t)__half_as_ushort(h[3]) << 16));
    uint2 ul = make_uint2(
        (uint32_t)__half_as_ushort(l[0]) | ((uint32_t)__half_as_ushort(l[1]) << 16),
        (uint32_t)__half_as_ushort(l[2]) | ((uint32_t)__half_as_ushort(l[3]) << 16));
    unsigned short* xp = (unsigned short*)g_x16 + row * KHL;
    *(uint2*)(xp + k)       = uh;
    *(uint2*)(xp + 256 + k) = ul;
}

// ---------------- kernel B: sum of squares per point ----------------
__global__ void sq_kernel(const float* __restrict__ x) {
    int row = blockIdx.x * 8 + threadIdx.y;
    const float4* p = (const float4*)(x + (size_t)row * DD);
    float s = 0.f;
#pragma unroll
    for (int i = 0; i < 2; i++) {
        float4 v = p[threadIdx.x + i * 32];
        s = fmaf(v.x, v.x, fmaf(v.y, v.y, fmaf(v.z, v.z, fmaf(v.w, v.w, s))));
    }
#pragma unroll
    for (int o = 16; o; o >>= 1) s += __shfl_xor_sync(0xffffffffu, s, o);
    if (threadIdx.x == 0) g_sq[row] = s;
}

// ---------------- mma helpers ----------------
__device__ __forceinline__ void ldmx4(uint32_t* r, uint32_t addr) {
    asm volatile("ldmatrix.sync.aligned.m8n8.x4.shared.b16 {%0,%1,%2,%3}, [%4];"
                 : "=r"(r[0]), "=r"(r[1]), "=r"(r[2]), "=r"(r[3]) : "r"(addr));
}
__device__ __forceinline__ void mma16816(float* d, const uint32_t* a, const uint32_t* b) {
    asm volatile("mma.sync.aligned.m16n8k16.row.col.f32.f16.f16.f32 "
                 "{%0,%1,%2,%3}, {%4,%5,%6,%7}, {%8,%9}, {%0,%1,%2,%3};"
                 : "+f"(d[0]), "+f"(d[1]), "+f"(d[2]), "+f"(d[3])
                 : "r"(a[0]), "r"(a[1]), "r"(a[2]), "r"(a[3]), "r"(b[0]), "r"(b[1]));
}
__device__ __forceinline__ void cp16(uint32_t dst, const void* src) {
    asm volatile("cp.async.cg.shared.global [%0], [%1], 16;" :: "r"(dst), "l"(src) : "memory");
}
__device__ __forceinline__ void ins5(float* t, float v) {
    if (v < t[4]) {
        float mm = v;
#pragma unroll
        for (int q = 0; q < 5; q++) {
            float cur = t[q];
            float lo = fminf(mm, cur);
            mm = fmaxf(mm, cur);
            t[q] = lo;
        }
    }
}

// ---------------- kernel C: symmetric mma.sync GEMM + fused kNN top-5 ----------------
// grid (272 upper-tri stripes, 8 batches), 512 threads = 16 warps (4M x 4N),
// stripe tile 128 (rows, tile I) x 256 (cols, stripe J2), K chunks of 64, 4-stage cp.async.
__global__ void __launch_bounds__(512, 1) knn_sym_kernel() {
    extern __shared__ __align__(128) char sm[];
    uint32_t smb;
    asm("{ .reg .u64 t; cvta.to.shared.u64 t, %1; cvt.u32.u64 %0, t; }" : "=r"(smb) : "l"(sm));

    const int tid = threadIdx.x;
    const int lane = tid & 31;
    const int warp = tid >> 5;
    const int wm = warp & 3;       // 0..3 (M, 32 rows each)
    const int wn = warp >> 2;      // 0..3 (N, 64 cols each)
    const int b  = blockIdx.y;

    // decode stripe index -> (I, J2), stripes with 2*J2+1 >= I
    int I = 0, off = 0;
    {
        int s = blockIdx.x;
        while (true) {
            int cnt = 16 - (I >> 1);
            if (s < off + cnt) { s -= off; I += 0; off = s; break; }
            off += cnt; I++;
        }
    }
    const int J2 = (I >> 1) + off;
    const int i0 = I * 128;
    const int j0 = J2 * 256;

    // loader precompute: 6 x 16B per thread (A rows 0..127 = k 0,1; B rows 0..255 = k 2..5)
    uint32_t soff[6];
    const __half* src[6];
#pragma unroll
    for (int k = 0; k < 6; k++) {
        int u = tid + k * 512;
        int row = u >> 3, q = u & 7;
        soff[k] = (uint32_t)(row * 128 + ((q ^ (row & 7)) * 16));
        if (row < 128) src[k] = g_x16 + ((size_t)(b * NN + i0 + row)) * KHL + q * 8;
        else           src[k] = g_x16 + ((size_t)(b * NN + j0 + (row - 128))) * KHL + q * 8;
    }
    auto issue = [&](int c) {
        const int ka = (c & 3) * 64 + ((c >= 8) ? 256 : 0);              // A: hi,hi,lo
        const int kb = (c & 3) * 64 + ((c >= 4 && c < 8) ? 256 : 0);     // B: hi,lo,hi
        const uint32_t base = smb + (c & 3) * STAGE_B;
        cp16(base + soff[0], src[0] + ka);
        cp16(base + soff[1], src[1] + ka);
#pragma unroll
        for (int k = 2; k < 6; k++) cp16(base + soff[k], src[k] + kb);
        asm volatile("cp.async.commit_group;" ::: "memory");
    };

    float acc[2][8][4];
#pragma unroll
    for (int mi = 0; mi < 2; mi++)
#pragma unroll
        for (int ni = 0; ni < 8; ni++)
#pragma unroll
            for (int v = 0; v < 4; v++) acc[mi][ni][v] = 0.f;

    issue(0); issue(1); issue(2);

    for (int c = 0; c < NCH; c++) {
        if (c < NCH - 2)       asm volatile("cp.async.wait_group 2;" ::: "memory");
        else if (c == NCH - 2) asm volatile("cp.async.wait_group 1;" ::: "memory");
        else                   asm volatile("cp.async.wait_group 0;" ::: "memory");
        __syncthreads();

        const uint32_t Ab = smb + (c & 3) * STAGE_B;
        const uint32_t Bb = Ab + 16384;

#pragma unroll
        for (int k16 = 0; k16 < 4; k16++) {
            uint32_t afr[2][4], bfr[8][2];
#pragma unroll
            for (int mi = 0; mi < 2; mi++) {
                int R = wm * 32 + mi * 16 + (lane & 15);
                int ul = k16 * 2 + (lane >> 4);
                ldmx4(afr[mi], Ab + R * 128 + ((ul ^ (R & 7)) * 16));
            }
#pragma unroll
            for (int np = 0; np < 4; np++) {
                int RB = wn * 64 + np * 16 + ((lane >> 4) << 3) + (lane & 7);
                int ul = k16 * 2 + ((lane >> 3) & 1);
                uint32_t r[4];
                ldmx4(r, Bb + RB * 128 + ((ul ^ (RB & 7)) * 16));
                bfr[np * 2][0] = r[0]; bfr[np * 2][1] = r[1];
                bfr[np * 2 + 1][0] = r[2]; bfr[np * 2 + 1][1] = r[3];
            }
#pragma unroll
            for (int mi = 0; mi < 2; mi++)
#pragma unroll
                for (int ni = 0; ni < 8; ni++)
                    mma16816(acc[mi][ni], afr[mi], bfr[ni]);
        }
        if (c + 3 < NCH) issue(c + 3);
    }

    // ---- row fold: rows of tile I, columns j >= i0 only ----
    int gi[4]; float sqi[4];
#pragma unroll
    for (int mi = 0; mi < 2; mi++)
#pragma unroll
        for (int h = 0; h < 2; h++) {
            int s = mi * 2 + h;
            gi[s] = i0 + wm * 32 + mi * 16 + (lane >> 2) + h * 8;
            sqi[s] = g_sq[b * NN + gi[s]];
        }
    float t5[4][5];
#pragma unroll
    for (int s = 0; s < 4; s++)
#pragma unroll
        for (int q = 0; q < 5; q++) t5[s][q] = INFINITY;

#pragma unroll
    for (int ni = 0; ni < 8; ni++)
#pragma unroll
        for (int cc = 0; cc < 2; cc++) {
            int gj = j0 + wn * 64 + ni * 8 + (lane & 3) * 2 + cc;
            if (gj >= i0) {
                float sqj = __ldg(&g_sq[b * NN + gj]);
#pragma unroll
                for (int mi = 0; mi < 2; mi++)
#pragma unroll
                    for (int h = 0; h < 2; h++) {
                        int s = mi * 2 + h;
                        float G = acc[mi][ni][h * 2 + cc];
                        float v = __fsub_rn(__fadd_rn(sqi[s], sqj), __fmul_rn(2.0f, G));
                        v = fmaxf(v, 0.0f);
                        if (gj == gi[s]) v = INFINITY;
                        ins5(t5[s], v);
                    }
            }
        }

    // ---- merge 16 owners per row, write g_part row slot J2 ----
    __syncthreads();
    float* MS = (float*)(sm + MS_OFF);   // 128 rows x 16 owners x 5 = 40KB
    const int owner = wn * 4 + (lane & 3);
#pragma unroll
    for (int s = 0; s < 4; s++) {
        int rloc = gi[s] - i0;
#pragma unroll
        for (int q = 0; q < 5; q++) MS[rloc * 80 + owner * 5 + q] = t5[s][q];
    }
    __syncthreads();
    if (tid < 128) {
        float best[5] = {INFINITY, INFINITY, INFINITY, INFINITY, INFINITY};
        for (int k = 0; k < 80; k++) ins5(best, MS[tid * 80 + k]);
        size_t o = ((size_t)J2 * BN * NN + (size_t)b * NN + i0 + tid) * 5;
#pragma unroll
        for (int q = 0; q < 5; q++) g_part[o + q] = best[q];
    }

    // ---- column folds for strictly-upper subtiles ----
    float* BUF = (float*)(sm + BUF_OFF);  // [128 cols][133]
    float* CM  = (float*)(sm + CM_OFF);   // [128 cols][20]
#pragma unroll
    for (int h = 0; h < 2; h++) {
        const int jt = 2 * J2 + h;
        if (jt <= I) continue;
        __syncthreads();
        if ((wn >> 1) == h) {
#pragma unroll
            for (int ni = 0; ni < 8; ni++)
#pragma unroll
                for (int cc = 0; cc < 2; cc++) {
                    int cl = (wn & 1) * 64 + ni * 8 + (lane & 3) * 2 + cc;
                    int gj = jt * 128 + cl;
                    float sqj = __ldg(&g_sq[b * NN + gj]);
#pragma unroll
                    for (int mi = 0; mi < 2; mi++)
#pragma unroll
                        for (int hh = 0; hh < 2; hh++) {
                            int s = mi * 2 + hh;
                            int rl = gi[s] - i0;
                            float G = acc[mi][ni][hh * 2 + cc];
                            float v = __fsub_rn(__fadd_rn(sqi[s], sqj), __fmul_rn(2.0f, G));
                            v = fmaxf(v, 0.0f);
                            BUF[cl * BUF_STRIDE + rl] = v;
                        }
                }
        }
        __syncthreads();
        {
            const int col = tid & 127;
            const int part = tid >> 7;     // 0..3, rows part*32..+32
            float best[5] = {INFINITY, INFINITY, INFINITY, INFINITY, INFINITY};
            const float* bp = BUF + col * BUF_STRIDE + part * 32;
#pragma unroll
            for (int r = 0; r < 32; r++) ins5(best, bp[r]);
#pragma unroll
            for (int q = 0; q < 5; q++) CM[col * 20 + part * 5 + q] = best[q];
        }
        __syncthreads();
        if (tid < 128) {
            float best[5] = {INFINITY, INFINITY, INFINITY, INFINITY, INFINITY};
#pragma unroll
            for (int k = 0; k < 20; k++) ins5(best, CM[tid * 20 + k]);
            size_t o = ((size_t)(16 + I) * BN * NN + (size_t)b * NN + jt * 128 + tid) * 5;
#pragma unroll
            for (int q = 0; q < 5; q++) g_part[o + q] = best[q];
        }
    }
}

// ---------------- kernel C2: merge partial top-5 lists ----------------
__global__ void merge_kernel() {
    int r = blockIdx.x * 256 + threadIdx.x;   // b*NN + i
    int i = r & (NN - 1);
    int T = i >> 7;
    float best[5] = {INFINITY, INFINITY, INFINITY, INFINITY, INFINITY};
    for (int J2 = (T >> 1); J2 < 16; J2++) {
        size_t o = ((size_t)J2 * BN * NN + r) * 5;
#pragma unroll
        for (int q = 0; q < 5; q++) ins5(best, g_part[o + q]);
    }
    for (int I2 = 0; I2 < T; I2++) {
        size_t o = ((size_t)(16 + I2) * BN * NN + r) * 5;
#pragma unroll
        for (int q = 0; q < 5; q++) ins5(best, g_part[o + q]);
    }
    g_dk2[r] = best[4];
}

// ---------------- threefry2x32, key = (0, 42) ----------------
__device__ __forceinline__ uint2 threefry_0_42(unsigned x0, unsigned x1) {
    const unsigned ks0 = 0u, ks1 = 42u;
    const unsigned ks2 = 0x1BD11BDAu ^ 42u;
    x0 += ks0; x1 += ks1;
#define ROTL(v, d) (((v) << (d)) | ((v) >> (32 - (d))))
#define RND(r) { x0 += x1; x1 = ROTL(x1, r); x1 ^= x0; }
    RND(13) RND(15) RND(26) RND(6)  x0 += ks1; x1 += ks2 + 1u;
    RND(17) RND(29) RND(16) RND(24) x0 += ks2; x1 += ks0 + 2u;
    RND(13) RND(15) RND(26) RND(6)  x0 += ks0; x1 += ks1 + 3u;
    RND(17) RND(29) RND(16) RND(24) x0 += ks1; x1 += ks2 + 4u;
    RND(13) RND(15) RND(26) RND(6)  x0 += ks2; x1 += ks0 + 5u;
#undef RND
#undef ROTL
    return make_uint2(x0, x1);
}

// ---------------- kernel D: scores + stable top-256 via bitonic sort ----------------
__global__ void score_sort_kernel() {
    __shared__ unsigned long long keys[NN];
    const int b = blockIdx.x;
    const int tid = threadIdx.x; // 1024
    const float TINY = 1.17549435e-38f;

    for (int n = tid; n < NN; n += 1024) {
        int jf = b * NN + n;
        uint2 y = threefry_0_42(0u, (unsigned)jf);
        unsigned bits = y.x ^ y.y;
        float u = __uint_as_float((bits >> 9) | 0x3f800000u) - 1.0f;
        float val = fmaxf(TINY, __fadd_rn(u, TINY));
        float g = -logf(-logf(val));
        float w = sqrtf(__fadd_rn(g_dk2[jf], 1e-12f));
        float score = __fadd_rn(logf(__fadd_rn(w, 1e-12f)), g);
        unsigned s = __float_as_uint(score);
        unsigned mono = (s & 0x80000000u) ? ~s : (s | 0x80000000u);
        keys[n] = ((unsigned long long)(~mono) << 32) | (unsigned)n;
    }
    __syncthreads();

    for (int k = 2; k <= NN; k <<= 1) {
        for (int j = k >> 1; j > 0; j >>= 1) {
            for (int i = tid; i < NN; i += 1024) {
                int ixj = i ^ j;
                if (ixj > i) {
                    bool up = ((i & k) == 0);
                    unsigned long long a = keys[i], c = keys[ixj];
                    if ((a > c) == up) { keys[i] = c; keys[ixj] = a; }
                }
            }
            __syncthreads();
        }
    }
    if (tid < SAMPK) g_sidx[b * SAMPK + tid] = (int)(keys[tid] & 0xffffffffu);
}

// ---------------- kernel E: gather + tail zero ----------------
__global__ void gather_kernel(const float* __restrict__ x, float* __restrict__ out, int out_size) {
    long gid = (long)blockIdx.x * 256 + threadIdx.x;
    if (gid >= out_size) return;
    const long SAMP = (long)BN * SAMPK * DD;
    if (gid < SAMP) {
        int d = (int)(gid & 255);
        int s = (int)((gid >> 8) & 255);
        int bb = (int)(gid >> 16);
        int idx = g_sidx[bb * SAMPK + s];
        out[gid] = x[((size_t)bb * NN + idx) * DD + d];
    } else {
        out[gid] = 0.0f;
    }
}

// ---------------- launch ----------------
extern "C" void kernel_launch(void* const* d_in, const int* in_sizes, int n_in,
                              void* d_out, int out_size) {
    const float* x = (const float*)d_in[0];
    float* out = (float*)d_out;

    static bool configured = false;
    if (!configured) {
        cudaFuncSetAttribute(knn_sym_kernel, cudaFuncAttributeMaxDynamicSharedMemorySize, KNN_SMEM);
        configured = true;
    }

    cvt_kernel<<<(BN * NN * DD) / (256 * 4), 256>>>(x);

    dim3 sqb(32, 8);
    sq_kernel<<<BN * NN / 8, sqb>>>(x);

    dim3 g1(NSTRIPE, BN);
    knn_sym_kernel<<<g1, 512, KNN_SMEM>>>();

    merge_kernel<<<BN * NN / 256, 256>>>();

    score_sort_kernel<<<BN, 1024>>>();

    long total = out_size;
    gather_kernel<<<(unsigned)((total + 255) / 256), 256>>>(x, out, (int)total);
}